// round 5
// baseline (speedup 1.0000x reference)
#include <cuda_runtime.h>
#include <math.h>

#define NB 8
#define ND 60
#define NP 1024
#define NK 20
#define NT (NP*NK)
#define SLOPE 0.2f

typedef unsigned long long ull;

// ---------------- device scratch ----------------
static __device__ float dg_pd[NB*NP*NP];
static __device__ float dg_xx[NB*NP];
static __device__ int   dg_idx[NB*NP*NK];
static __device__ float dg_P[NB*64*NP];
static __device__ float dg_S[NB*64*NP];
static __device__ float dg_h1[NB*64*NT];
static __device__ float dg_h2[NB*64*NT];
static __device__ float dg_h3[NB*128*NT];
static __device__ float dg_z [NB*512*NP];
static __device__ float dg_o5[NB*256*NP];
static __device__ float dg_o6[NB*1024*NP];
static __device__ double dg_sum[6][1024];
static __device__ double dg_ssq[6][1024];
static __device__ float dg_scZ[512], dg_shZ[512];
static __device__ float dg_sc5[256], dg_sh5[256];
static __device__ float dg_sc6[1024], dg_sh6[1024];

// packed fp32x2 FMA (sm_103a) — exact fp32 numerics per lane, 2x rate
#define FMA2(d, a, bb) asm("fma.rn.f32x2 %0, %1, %2, %0;" : "+l"(d) : "l"(a), "l"(bb))
#define DUP2(d, f)     asm("mov.b64 %0, {%1, %1};" : "=l"(d) : "f"(f))
#define UNPK2(lo, hi, d) asm("mov.b64 {%0, %1}, %2;" : "=f"(lo), "=f"(hi) : "l"(d))

#define LRELU4(v, s, h)                                           \
    v.x = fmaf(v.x, s, h); v.x = v.x >= 0.f ? v.x : SLOPE*v.x;    \
    v.y = fmaf(v.y, s, h); v.y = v.y >= 0.f ? v.y : SLOPE*v.y;    \
    v.z = fmaf(v.z, s, h); v.z = v.z >= 0.f ? v.z : SLOPE*v.z;    \
    v.w = fmaf(v.w, s, h); v.w = v.w >= 0.f ? v.w : SLOPE*v.w;

// ---------------- small kernels ----------------

__global__ void k_zero() {
    int i = blockIdx.x*1024 + threadIdx.x;
    ((double*)dg_sum)[i] = 0.0;
    ((double*)dg_ssq)[i] = 0.0;
}

__global__ void k_xx(const float* __restrict__ x) {
    int b = blockIdx.x, n = threadIdx.x;
    float s = 0.f;
    #pragma unroll
    for (int d = 0; d < ND; d++) {
        float v = x[((size_t)b*ND + d)*NP + n];
        s = fmaf(v, v, s);
    }
    dg_xx[b*NP + n] = s;
}

// pd[b,n,m] = 2*dot(x_n,x_m) - xx_n - xx_m
__global__ void __launch_bounds__(128) k_pdist(const float* __restrict__ x) {
    __shared__ float sn[ND][32], sm[ND][32];
    int b = blockIdx.z;
    int n0 = blockIdx.y*32, m0 = blockIdx.x*32;
    int tx = threadIdx.x, ty = threadIdx.y;
    int tid = ty*8 + tx;
    for (int e = tid; e < ND*32; e += 128) {
        int d = e >> 5, c = e & 31;
        size_t base = ((size_t)b*ND + d)*NP;
        sn[d][c] = x[base + n0 + c];
        sm[d][c] = x[base + m0 + c];
    }
    __syncthreads();
    ull acc[2][2] = {{0ull,0ull},{0ull,0ull}};
    #pragma unroll
    for (int d = 0; d < ND; d++) {
        ull sn2 = *(const ull*)&sn[d][ty*2];
        float nlo, nhi; UNPK2(nlo, nhi, sn2);
        ull dlo, dhi; DUP2(dlo, nlo); DUP2(dhi, nhi);
        ull mp0 = *(const ull*)&sm[d][tx*4];
        ull mp1 = *(const ull*)&sm[d][tx*4+2];
        FMA2(acc[0][0], mp0, dlo); FMA2(acc[0][1], mp1, dlo);
        FMA2(acc[1][0], mp0, dhi); FMA2(acc[1][1], mp1, dhi);
    }
    float xm[4];
    #pragma unroll
    for (int j = 0; j < 4; j++) xm[j] = dg_xx[b*NP + m0 + tx*4 + j];
    #pragma unroll
    for (int i = 0; i < 2; i++) {
        int n = n0 + ty*2 + i;
        float xn = dg_xx[b*NP + n];
        float v0, v1, v2, v3;
        UNPK2(v0, v1, acc[i][0]);
        UNPK2(v2, v3, acc[i][1]);
        float4 o = make_float4(2.f*v0 - xn - xm[0], 2.f*v1 - xn - xm[1],
                               2.f*v2 - xn - xm[2], 2.f*v3 - xn - xm[3]);
        *(float4*)(dg_pd + ((size_t)b*NP + n)*NP + m0 + tx*4) = o;
    }
}

// warp-per-row top-20 with cached per-lane (max, slot); only the winning
// lane rescans its 32 values per extraction. Tie-break: lowest global index
// (within a lane, global idx is strictly increasing in slot; across lanes
// the shfl-reduce prefers lower idx on equal value) — matches jax top_k.
__global__ void k_topk() {
    int warp = threadIdx.x >> 5, lane = threadIdx.x & 31;
    int row = blockIdx.x*8 + warp;
    const float* rp = dg_pd + (size_t)row*NP;
    float v[32];
    #pragma unroll
    for (int i = 0; i < 8; i++) {
        float4 t = *(const float4*)(rp + i*128 + lane*4);
        v[i*4+0] = t.x; v[i*4+1] = t.y; v[i*4+2] = t.z; v[i*4+3] = t.w;
    }
    float lmax = v[0]; int ls = 0;
    #pragma unroll
    for (int s = 1; s < 32; s++) if (v[s] > lmax) { lmax = v[s]; ls = s; }

    int* outp = dg_idx + (size_t)row*NK;
    for (int t = 0; t < NK; t++) {
        float best = lmax;
        int bi = ((ls >> 2) << 7) + (lane << 2) + (ls & 3);
        #pragma unroll
        for (int d = 16; d; d >>= 1) {
            float ov = __shfl_xor_sync(0xffffffffu, best, d);
            int   oi = __shfl_xor_sync(0xffffffffu, bi, d);
            if (ov > best || (ov == best && oi < bi)) { best = ov; bi = oi; }
        }
        if (lane == 0) outp[t] = bi;
        int wl = (bi >> 2) & 31;
        if (lane == wl) {
            int ws = ((bi >> 7) << 2) | (bi & 3);
            lmax = -INFINITY; ls = 0;
            #pragma unroll
            for (int s = 0; s < 32; s++) {
                if (s == ws) v[s] = -INFINITY;
                if (v[s] > lmax) { lmax = v[s]; ls = s; }
            }
        }
    }
}

__global__ void k_ps(const float* __restrict__ x, const float* __restrict__ w1) {
    __shared__ float wa[ND], ws[ND];
    int o = blockIdx.y, b = blockIdx.z, tid = threadIdx.x;
    if (tid < ND) {
        float a = w1[o*120 + tid];
        wa[tid] = a;
        ws[tid] = w1[o*120 + 60 + tid] - a;
    }
    __syncthreads();
    int n = blockIdx.x*256 + tid;
    float p = 0.f, s = 0.f;
    #pragma unroll
    for (int d = 0; d < ND; d++) {
        float xv = x[((size_t)b*ND + d)*NP + n];
        p = fmaf(wa[d], xv, p);
        s = fmaf(ws[d], xv, s);
    }
    dg_P[((size_t)b*64 + o)*NP + n] = p;
    dg_S[((size_t)b*64 + o)*NP + n] = s;
}

__global__ void k_h1(const float* __restrict__ b1) {
    int tid = threadIdx.x;
    int n = blockIdx.x*256 + tid;
    int o = blockIdx.y, b = blockIdx.z;
    float sv = dg_S[((size_t)b*64 + o)*NP + n] + b1[o];
    const float* Pb = dg_P + ((size_t)b*64 + o)*NP;
    const int* ip = dg_idx + ((size_t)b*NP + n)*NK;
    float vals[NK];
    float sum = 0.f, ss = 0.f, mx = -INFINITY;
    #pragma unroll
    for (int j = 0; j < NK; j++) {
        float v = Pb[ip[j]] + sv;
        vals[j] = v;
        sum += v;
        ss = fmaf(v, v, ss);
        mx = fmaxf(mx, v);
    }
    float* dst = dg_h1 + (((size_t)b*64 + o)*NP + n)*NK;
    #pragma unroll
    for (int j4 = 0; j4 < 5; j4++)
        ((float4*)dst)[j4] = make_float4(vals[4*j4], vals[4*j4+1], vals[4*j4+2], vals[4*j4+3]);
    dg_z[((size_t)b*512 + o)*NP + n] = mx;

    #pragma unroll
    for (int d = 1; d < 32; d <<= 1) {
        sum += __shfl_xor_sync(0xffffffffu, sum, d);
        ss  += __shfl_xor_sync(0xffffffffu, ss, d);
    }
    if ((tid & 31) == 0) {
        atomicAdd(&dg_sum[0][o], (double)sum);
        atomicAdd(&dg_ssq[0][o], (double)ss);
    }
}

__global__ void k_finalize(int stage, int C, float cnt,
                           const float* __restrict__ g, const float* __restrict__ be,
                           float* __restrict__ sc, float* __restrict__ sh) {
    int c = threadIdx.x;
    if (c < C) {
        double mu  = dg_sum[stage][c] / (double)cnt;
        double var = dg_ssq[stage][c] / (double)cnt - mu*mu;
        float scale = g[c] * (float)(1.0 / sqrt(var + 1e-5));
        sc[c] = scale;
        sh[c] = be[c] - (float)mu * scale;
    }
}

// ====== edge-domain SGEMM: FFMA2, double-buffered smem, fused stats+max =====
template<int MI, bool WRITE>
__global__ void __launch_bounds__(256) k_egemm(
        const float* __restrict__ A, const float* __restrict__ W,
        const float* __restrict__ bias,
        const float* __restrict__ sc, const float* __restrict__ sh,
        float* __restrict__ Out, int M, int K, int stage, int zoff) {
    __shared__ float As[2][16][160];
    __shared__ float Ws[2][16][MI*16 + 8];
    const int NW = MI/4;
    int b = blockIdx.z;
    const float* Ab = A + (size_t)b*K*NT;
    int m0 = blockIdx.y*(MI*16), t0 = blockIdx.x*160;
    int tid = threadIdx.x, tx = tid & 15, ty = tid >> 4;

    int ar[3], ac[3];
    #pragma unroll
    for (int i = 0; i < 3; i++) { int e = tid + i*256; ar[i] = e/40; ac[i] = (e%40)*4; }

    ull acc[MI][5];
    #pragma unroll
    for (int i = 0; i < MI; i++)
        #pragma unroll
        for (int q = 0; q < 5; q++) acc[i][q] = 0ull;

    float4 pa[3]; float aps[3], aph[3];
    float4 pw[NW];

    // prefetch + store tile 0
    #pragma unroll
    for (int i = 0; i < 3; i++) if (tid + i*256 < 640) {
        pa[i] = *(const float4*)(Ab + (size_t)ar[i]*NT + t0 + ac[i]);
        aps[i] = sc[ar[i]]; aph[i] = sh[ar[i]];
    }
    #pragma unroll
    for (int i = 0; i < NW; i++) {
        int e = tid + i*256; int r = e >> 2, c = (e & 3)*4;
        pw[i] = *(const float4*)(W + (size_t)(m0+r)*K + c);
    }
    #pragma unroll
    for (int i = 0; i < 3; i++) if (tid + i*256 < 640) {
        float4 v = pa[i]; float s = aps[i], h = aph[i];
        LRELU4(v, s, h);
        *(float4*)&As[0][ar[i]][ac[i]] = v;
    }
    #pragma unroll
    for (int i = 0; i < NW; i++) {
        int e = tid + i*256; int r = e >> 2, c = (e & 3)*4;
        Ws[0][c+0][r] = pw[i].x; Ws[0][c+1][r] = pw[i].y;
        Ws[0][c+2][r] = pw[i].z; Ws[0][c+3][r] = pw[i].w;
    }

    int KT = K >> 4;
    for (int kt = 0; kt < KT; kt++) {
        __syncthreads();
        int cb = kt & 1;
        int k1 = (kt + 1) << 4;
        if (kt + 1 < KT) {
            #pragma unroll
            for (int i = 0; i < 3; i++) if (tid + i*256 < 640) {
                pa[i] = *(const float4*)(Ab + (size_t)(k1+ar[i])*NT + t0 + ac[i]);
                aps[i] = sc[k1+ar[i]]; aph[i] = sh[k1+ar[i]];
            }
            #pragma unroll
            for (int i = 0; i < NW; i++) {
                int e = tid + i*256; int r = e >> 2, c = (e & 3)*4;
                pw[i] = *(const float4*)(W + (size_t)(m0+r)*K + k1 + c);
            }
        }
        #pragma unroll
        for (int kk = 0; kk < 16; kk++) {
            const ull* arow = (const ull*)&As[cb][kk][tx*10];
            ull ap[5];
            #pragma unroll
            for (int q = 0; q < 5; q++) ap[q] = arow[q];
            float wv[MI];
            #pragma unroll
            for (int h = 0; h < MI; h += 4) {
                float4 wf = *(const float4*)&Ws[cb][kk][ty*MI + h];
                wv[h] = wf.x; wv[h+1] = wf.y; wv[h+2] = wf.z; wv[h+3] = wf.w;
            }
            #pragma unroll
            for (int i = 0; i < MI; i++) {
                ull wp; DUP2(wp, wv[i]);
                #pragma unroll
                for (int q = 0; q < 5; q++) FMA2(acc[i][q], ap[q], wp);
            }
        }
        if (kt + 1 < KT) {
            int nb = 1 - cb;
            #pragma unroll
            for (int i = 0; i < 3; i++) if (tid + i*256 < 640) {
                float4 v = pa[i]; float s = aps[i], h = aph[i];
                LRELU4(v, s, h);
                *(float4*)&As[nb][ar[i]][ac[i]] = v;
            }
            #pragma unroll
            for (int i = 0; i < NW; i++) {
                int e = tid + i*256; int r = e >> 2, c = (e & 3)*4;
                Ws[nb][c+0][r] = pw[i].x; Ws[nb][c+1][r] = pw[i].y;
                Ws[nb][c+2][r] = pw[i].z; Ws[nb][c+3][r] = pw[i].w;
            }
        }
    }

    float* Ob = WRITE ? (Out + (size_t)b*M*NT) : (float*)0;
    #pragma unroll
    for (int i = 0; i < MI; i++) {
        int m = m0 + ty*MI + i;
        float bv = bias[m];
        float sum = 0.f, ss = 0.f, mxv = -INFINITY;
        #pragma unroll
        for (int q = 0; q < 5; q++) {
            float lo, hi;
            UNPK2(lo, hi, acc[i][q]);
            lo += bv; hi += bv;
            if (WRITE)
                *(float2*)(Ob + (size_t)m*NT + t0 + tx*10 + 2*q) = make_float2(lo, hi);
            sum += lo + hi;
            ss = fmaf(lo, lo, ss); ss = fmaf(hi, hi, ss);
            mxv = fmaxf(mxv, fmaxf(lo, hi));
        }
        #pragma unroll
        for (int d = 1; d < 16; d <<= 1) {
            sum += __shfl_xor_sync(0xffffffffu, sum, d);
            ss  += __shfl_xor_sync(0xffffffffu, ss, d);
        }
        if (tx == 0) {
            atomicAdd(&dg_sum[stage][m], (double)sum);
            atomicAdd(&dg_ssq[stage][m], (double)ss);
        }
        float mo = fmaxf(mxv, __shfl_xor_sync(0xffffffffu, mxv, 1));
        if ((tx & 1) == 0)
            dg_z[((size_t)b*512 + zoff + m)*NP + blockIdx.x*8 + (tx >> 1)] = mo;
    }
}

// ====== point-domain SGEMM: FFMA2, double-buffered smem, fused stats =======
template<int MI>
__global__ void __launch_bounds__(256) k_pgemm(
        const float* __restrict__ A, const float* __restrict__ W,
        const float* __restrict__ bias,
        const float* __restrict__ sc, const float* __restrict__ sh,
        float* __restrict__ Out, int M, int K, int stage) {
    __shared__ float As[2][16][128];
    __shared__ float Ws[2][16][MI*16 + 8];
    const int NW = MI/4;
    int b = blockIdx.z;
    const float* Ab = A + (size_t)b*K*NP;
    float* Ob = Out + (size_t)b*M*NP;
    int m0 = blockIdx.y*(MI*16), t0 = blockIdx.x*128;
    int tid = threadIdx.x, tx = tid & 15, ty = tid >> 4;

    ull acc[MI][4];
    #pragma unroll
    for (int i = 0; i < MI; i++)
        #pragma unroll
        for (int q = 0; q < 4; q++) acc[i][q] = 0ull;

    float4 pa[2]; float aps[2], aph[2];
    float4 pw[NW];
    int ar[2], ac[2];
    #pragma unroll
    for (int i = 0; i < 2; i++) { int e = tid + i*256; ar[i] = e >> 5; ac[i] = (e & 31)*4; }

    #pragma unroll
    for (int i = 0; i < 2; i++) {
        pa[i] = *(const float4*)(Ab + (size_t)ar[i]*NP + t0 + ac[i]);
        aps[i] = sc[ar[i]]; aph[i] = sh[ar[i]];
    }
    #pragma unroll
    for (int i = 0; i < NW; i++) {
        int e = tid + i*256; int r = e >> 2, c = (e & 3)*4;
        pw[i] = *(const float4*)(W + (size_t)(m0+r)*K + c);
    }
    #pragma unroll
    for (int i = 0; i < 2; i++) {
        float4 v = pa[i]; float s = aps[i], h = aph[i];
        LRELU4(v, s, h);
        *(float4*)&As[0][ar[i]][ac[i]] = v;
    }
    #pragma unroll
    for (int i = 0; i < NW; i++) {
        int e = tid + i*256; int r = e >> 2, c = (e & 3)*4;
        Ws[0][c+0][r] = pw[i].x; Ws[0][c+1][r] = pw[i].y;
        Ws[0][c+2][r] = pw[i].z; Ws[0][c+3][r] = pw[i].w;
    }

    int KT = K >> 4;
    for (int kt = 0; kt < KT; kt++) {
        __syncthreads();
        int cb = kt & 1;
        int k1 = (kt + 1) << 4;
        if (kt + 1 < KT) {
            #pragma unroll
            for (int i = 0; i < 2; i++) {
                pa[i] = *(const float4*)(Ab + (size_t)(k1+ar[i])*NP + t0 + ac[i]);
                aps[i] = sc[k1+ar[i]]; aph[i] = sh[k1+ar[i]];
            }
            #pragma unroll
            for (int i = 0; i < NW; i++) {
                int e = tid + i*256; int r = e >> 2, c = (e & 3)*4;
                pw[i] = *(const float4*)(W + (size_t)(m0+r)*K + k1 + c);
            }
        }
        #pragma unroll
        for (int kk = 0; kk < 16; kk++) {
            const ull* arow = (const ull*)&As[cb][kk][0];
            ull ap[4];
            #pragma unroll
            for (int q = 0; q < 4; q++) ap[q] = arow[tx + 16*q];
            float wv[MI];
            #pragma unroll
            for (int h = 0; h < MI; h += 4) {
                float4 wf = *(const float4*)&Ws[cb][kk][ty*MI + h];
                wv[h] = wf.x; wv[h+1] = wf.y; wv[h+2] = wf.z; wv[h+3] = wf.w;
            }
            #pragma unroll
            for (int i = 0; i < MI; i++) {
                ull wp; DUP2(wp, wv[i]);
                #pragma unroll
                for (int q = 0; q < 4; q++) FMA2(acc[i][q], ap[q], wp);
            }
        }
        if (kt + 1 < KT) {
            int nb = 1 - cb;
            #pragma unroll
            for (int i = 0; i < 2; i++) {
                float4 v = pa[i]; float s = aps[i], h = aph[i];
                LRELU4(v, s, h);
                *(float4*)&As[nb][ar[i]][ac[i]] = v;
            }
            #pragma unroll
            for (int i = 0; i < NW; i++) {
                int e = tid + i*256; int r = e >> 2, c = (e & 3)*4;
                Ws[nb][c+0][r] = pw[i].x; Ws[nb][c+1][r] = pw[i].y;
                Ws[nb][c+2][r] = pw[i].z; Ws[nb][c+3][r] = pw[i].w;
            }
        }
    }

    #pragma unroll
    for (int i = 0; i < MI; i++) {
        int m = m0 + ty*MI + i;
        float bv = bias[m];
        float sum = 0.f, ss = 0.f;
        #pragma unroll
        for (int q = 0; q < 4; q++) {
            float lo, hi;
            UNPK2(lo, hi, acc[i][q]);
            lo += bv; hi += bv;
            *(float2*)(Ob + (size_t)m*NP + t0 + 2*tx + 32*q) = make_float2(lo, hi);
            sum += lo + hi;
            ss = fmaf(lo, lo, ss); ss = fmaf(hi, hi, ss);
        }
        #pragma unroll
        for (int d = 1; d < 16; d <<= 1) {
            sum += __shfl_xor_sync(0xffffffffu, sum, d);
            ss  += __shfl_xor_sync(0xffffffffu, ss, d);
        }
        if (tx == 0) {
            atomicAdd(&dg_sum[stage][m], (double)sum);
            atomicAdd(&dg_ssq[stage][m], (double)ss);
        }
    }
}

// final bn+lrelu + (B,C,N) -> (B,N,C) transpose
__global__ void k_out(float* __restrict__ out) {
    __shared__ float st[32][33];
    int b = blockIdx.z;
    int c0 = blockIdx.y*32, n0 = blockIdx.x*32;
    int tx = threadIdx.x, ty = threadIdx.y;
    int c = c0 + ty;
    float v = dg_o6[((size_t)b*1024 + c)*NP + n0 + tx];
    v = fmaf(v, dg_sc6[c], dg_sh6[c]);
    st[ty][tx] = v >= 0.f ? v : SLOPE*v;
    __syncthreads();
    out[((size_t)b*NP + n0 + ty)*1024 + c0 + tx] = st[tx][ty];
}

// ---------------- host orchestration ----------------

extern "C" void kernel_launch(void* const* d_in, const int* in_sizes, int n_in,
                              void* d_out, int out_size) {
    (void)in_sizes; (void)n_in; (void)out_size;
    const float* x  = (const float*)d_in[0];
    const float* w1 = (const float*)d_in[1];
    const float* b1 = (const float*)d_in[2];
    const float* g1 = (const float*)d_in[3];
    const float* be1= (const float*)d_in[4];
    const float* w2 = (const float*)d_in[5];
    const float* b2 = (const float*)d_in[6];
    const float* g2 = (const float*)d_in[7];
    const float* be2= (const float*)d_in[8];
    const float* w3 = (const float*)d_in[9];
    const float* b3 = (const float*)d_in[10];
    const float* g3 = (const float*)d_in[11];
    const float* be3= (const float*)d_in[12];
    const float* w4 = (const float*)d_in[13];
    const float* b4 = (const float*)d_in[14];
    const float* g4 = (const float*)d_in[15];
    const float* be4= (const float*)d_in[16];
    const float* w5 = (const float*)d_in[17];
    const float* b5 = (const float*)d_in[18];
    const float* g5 = (const float*)d_in[19];
    const float* be5= (const float*)d_in[20];
    const float* w6 = (const float*)d_in[21];
    const float* b6 = (const float*)d_in[22];
    const float* g6 = (const float*)d_in[23];
    const float* be6= (const float*)d_in[24];

    float *p_h1, *p_h2, *p_h3, *p_z, *p_o5, *p_o6;
    float *p_scZ, *p_shZ, *p_sc5, *p_sh5, *p_sc6, *p_sh6;
    cudaGetSymbolAddress((void**)&p_h1, dg_h1);
    cudaGetSymbolAddress((void**)&p_h2, dg_h2);
    cudaGetSymbolAddress((void**)&p_h3, dg_h3);
    cudaGetSymbolAddress((void**)&p_z,  dg_z);
    cudaGetSymbolAddress((void**)&p_o5, dg_o5);
    cudaGetSymbolAddress((void**)&p_o6, dg_o6);
    cudaGetSymbolAddress((void**)&p_scZ, dg_scZ);
    cudaGetSymbolAddress((void**)&p_shZ, dg_shZ);
    cudaGetSymbolAddress((void**)&p_sc5, dg_sc5);
    cudaGetSymbolAddress((void**)&p_sh5, dg_sh5);
    cudaGetSymbolAddress((void**)&p_sc6, dg_sc6);
    cudaGetSymbolAddress((void**)&p_sh6, dg_sh6);

    const float cntE = (float)(NB*NP*NK);
    const float cntP = (float)(NB*NP);

    k_zero<<<6, 1024>>>();
    k_xx<<<NB, NP>>>(x);
    k_pdist<<<dim3(NP/32, NP/32, NB), dim3(8, 16)>>>(x);
    k_topk<<<NB*NP/8, 256>>>();
    k_ps<<<dim3(NP/256, 64, NB), 256>>>(x, w1);

    k_h1<<<dim3(NP/256, 64, NB), 256>>>(b1);
    k_finalize<<<1, 64>>>(0, 64, cntE, g1, be1, p_scZ, p_shZ);

    // conv2: 64 <- 64 (MI=4)
    k_egemm<4, true><<<dim3(NT/160, 1, NB), 256>>>(p_h1, w2, b2, p_scZ, p_shZ, p_h2, 64, 64, 1, 64);
    k_finalize<<<1, 64>>>(1, 64, cntE, g2, be2, p_scZ + 64, p_shZ + 64);

    // conv3: 128 <- 64 (MI=8)
    k_egemm<8, true><<<dim3(NT/160, 1, NB), 256>>>(p_h2, w3, b3, p_scZ + 64, p_shZ + 64, p_h3, 128, 64, 2, 128);
    k_finalize<<<1, 128>>>(2, 128, cntE, g3, be3, p_scZ + 128, p_shZ + 128);

    // conv4: 256 <- 128, stats+max only (no output tensor)
    k_egemm<8, false><<<dim3(NT/160, 2, NB), 256>>>(p_h3, w4, b4, p_scZ + 128, p_shZ + 128, (float*)0, 256, 128, 3, 256);
    k_finalize<<<1, 256>>>(3, 256, cntE, g4, be4, p_scZ + 256, p_shZ + 256);

    // conv5: 256 <- 512 over points
    k_pgemm<8><<<dim3(NP/128, 2, NB), 256>>>(p_z, w5, b5, p_scZ, p_shZ, p_o5, 256, 512, 4);
    k_finalize<<<1, 256>>>(4, 256, cntP, g5, be5, p_sc5, p_sh5);

    // conv6: 1024 <- 256
    k_pgemm<8><<<dim3(NP/128, 8, NB), 256>>>(p_o5, w6, b6, p_sc5, p_sh5, p_o6, 1024, 256, 5);
    k_finalize<<<1, 1024>>>(5, 1024, cntP, g6, be6, p_sc6, p_sh6);

    k_out<<<dim3(NP/32, 1024/32, NB), dim3(32, 32)>>>((float*)d_out);
}

// round 6
// speedup vs baseline: 1.6456x; 1.6456x over previous
#include <cuda_runtime.h>
#include <math.h>

#define NB 8
#define ND 60
#define NP 1024
#define NK 20
#define NT (NP*NK)
#define SLOPE 0.2f

typedef unsigned long long ull;

// ---------------- device scratch ----------------
static __device__ float dg_pd[NB*NP*NP];
static __device__ float dg_xx[NB*NP];
static __device__ int   dg_idx[NB*NP*NK];
static __device__ float dg_P[NB*64*NP];
static __device__ float dg_S[NB*64*NP];
static __device__ float dg_h1[NB*64*NT];
static __device__ float dg_h2[NB*64*NT];
static __device__ float dg_h3[NB*128*NT];
static __device__ float dg_z [NB*512*NP];
static __device__ float dg_o5[NB*256*NP];
static __device__ float dg_o6[NB*1024*NP];
static __device__ double dg_sum[6][1024];
static __device__ double dg_ssq[6][1024];
static __device__ float dg_scZ[512], dg_shZ[512];
static __device__ float dg_sc5[256], dg_sh5[256];
static __device__ float dg_sc6[1024], dg_sh6[1024];

// packed fp32x2 FMA (sm_103a) — exact fp32 numerics per lane, 2x rate
#define FMA2(d, a, bb) asm("fma.rn.f32x2 %0, %1, %2, %0;" : "+l"(d) : "l"(a), "l"(bb))
#define DUP2(d, f)     asm("mov.b64 %0, {%1, %1};" : "=l"(d) : "f"(f))
#define UNPK2(lo, hi, d) asm("mov.b64 {%0, %1}, %2;" : "=f"(lo), "=f"(hi) : "l"(d))

#define LRELU4(v, s, h)                                           \
    v.x = fmaf(v.x, s, h); v.x = v.x >= 0.f ? v.x : SLOPE*v.x;    \
    v.y = fmaf(v.y, s, h); v.y = v.y >= 0.f ? v.y : SLOPE*v.y;    \
    v.z = fmaf(v.z, s, h); v.z = v.z >= 0.f ? v.z : SLOPE*v.z;    \
    v.w = fmaf(v.w, s, h); v.w = v.w >= 0.f ? v.w : SLOPE*v.w;

// ---------------- small kernels ----------------

__global__ void k_zero() {
    int i = blockIdx.x*1024 + threadIdx.x;
    ((double*)dg_sum)[i] = 0.0;
    ((double*)dg_ssq)[i] = 0.0;
}

__global__ void k_xx(const float* __restrict__ x) {
    int b = blockIdx.x, n = threadIdx.x;
    float s = 0.f;
    #pragma unroll
    for (int d = 0; d < ND; d++) {
        float v = x[((size_t)b*ND + d)*NP + n];
        s = fmaf(v, v, s);
    }
    dg_xx[b*NP + n] = s;
}

// pd[b,n,m] = 2*dot(x_n,x_m) - xx_n - xx_m
__global__ void __launch_bounds__(128) k_pdist(const float* __restrict__ x) {
    __shared__ float sn[ND][32], sm[ND][32];
    int b = blockIdx.z;
    int n0 = blockIdx.y*32, m0 = blockIdx.x*32;
    int tx = threadIdx.x, ty = threadIdx.y;
    int tid = ty*8 + tx;
    for (int e = tid; e < ND*32; e += 128) {
        int d = e >> 5, c = e & 31;
        size_t base = ((size_t)b*ND + d)*NP;
        sn[d][c] = x[base + n0 + c];
        sm[d][c] = x[base + m0 + c];
    }
    __syncthreads();
    ull acc[2][2] = {{0ull,0ull},{0ull,0ull}};
    #pragma unroll
    for (int d = 0; d < ND; d++) {
        ull sn2 = *(const ull*)&sn[d][ty*2];
        float nlo, nhi; UNPK2(nlo, nhi, sn2);
        ull dlo, dhi; DUP2(dlo, nlo); DUP2(dhi, nhi);
        ull mp0 = *(const ull*)&sm[d][tx*4];
        ull mp1 = *(const ull*)&sm[d][tx*4+2];
        FMA2(acc[0][0], mp0, dlo); FMA2(acc[0][1], mp1, dlo);
        FMA2(acc[1][0], mp0, dhi); FMA2(acc[1][1], mp1, dhi);
    }
    float xm[4];
    #pragma unroll
    for (int j = 0; j < 4; j++) xm[j] = dg_xx[b*NP + m0 + tx*4 + j];
    #pragma unroll
    for (int i = 0; i < 2; i++) {
        int n = n0 + ty*2 + i;
        float xn = dg_xx[b*NP + n];
        float v0, v1, v2, v3;
        UNPK2(v0, v1, acc[i][0]);
        UNPK2(v2, v3, acc[i][1]);
        float4 o = make_float4(2.f*v0 - xn - xm[0], 2.f*v1 - xn - xm[1],
                               2.f*v2 - xn - xm[2], 2.f*v3 - xn - xm[3]);
        *(float4*)(dg_pd + ((size_t)b*NP + n)*NP + m0 + tx*4) = o;
    }
}

// warp-per-row top-20 via per-lane bitonic sort of 32 packed (value,idx)
// 64-bit keys. key = orderable(v)<<32 | (~idx) -> single ull compare gives
// (value desc, idx asc), matching jax top_k tie-break. Extraction: 20 rounds
// of warp shfl-max over lane heads; winner lane shifts its sorted list.
__global__ void k_topk() {
    int warp = threadIdx.x >> 5, lane = threadIdx.x & 31;
    int row = blockIdx.x*8 + warp;
    const float* rp = dg_pd + (size_t)row*NP;
    ull k[32];
    #pragma unroll
    for (int i = 0; i < 8; i++) {
        float4 t = *(const float4*)(rp + i*128 + lane*4);
        float vv[4] = {t.x, t.y, t.z, t.w};
        #pragma unroll
        for (int j = 0; j < 4; j++) {
            unsigned fb = __float_as_uint(vv[j]);
            unsigned u = (fb & 0x80000000u) ? ~fb : (fb | 0x80000000u);
            unsigned idx = (unsigned)(i*128 + lane*4 + j);
            k[i*4+j] = ((ull)u << 32) | (ull)(0xFFFFFFFFu - idx);
        }
    }
    // bitonic sort, descending
    #pragma unroll
    for (int sz = 2; sz <= 32; sz <<= 1) {
        #pragma unroll
        for (int st = sz >> 1; st > 0; st >>= 1) {
            #pragma unroll
            for (int i = 0; i < 32; i++) {
                int j = i ^ st;
                if (j > i) {
                    bool sw = ((i & sz) == 0) ? (k[i] < k[j]) : (k[i] > k[j]);
                    if (sw) { ull t = k[i]; k[i] = k[j]; k[j] = t; }
                }
            }
        }
    }
    int* outp = dg_idx + (size_t)row*NK;
    #pragma unroll
    for (int t = 0; t < NK; t++) {
        ull best = k[0];
        #pragma unroll
        for (int d = 16; d; d >>= 1) {
            ull o = __shfl_xor_sync(0xffffffffu, best, d);
            if (o > best) best = o;
        }
        if (lane == 0) outp[t] = (int)(0xFFFFFFFFu - (unsigned)(best & 0xFFFFFFFFull));
        if (k[0] == best) {
            #pragma unroll
            for (int j = 0; j < 20; j++) k[j] = k[j+1];
        }
    }
}

__global__ void k_ps(const float* __restrict__ x, const float* __restrict__ w1) {
    __shared__ float wa[ND], ws[ND];
    int o = blockIdx.y, b = blockIdx.z, tid = threadIdx.x;
    if (tid < ND) {
        float a = w1[o*120 + tid];
        wa[tid] = a;
        ws[tid] = w1[o*120 + 60 + tid] - a;
    }
    __syncthreads();
    int n = blockIdx.x*256 + tid;
    float p = 0.f, s = 0.f;
    #pragma unroll
    for (int d = 0; d < ND; d++) {
        float xv = x[((size_t)b*ND + d)*NP + n];
        p = fmaf(wa[d], xv, p);
        s = fmaf(ws[d], xv, s);
    }
    dg_P[((size_t)b*64 + o)*NP + n] = p;
    dg_S[((size_t)b*64 + o)*NP + n] = s;
}

__global__ void k_h1(const float* __restrict__ b1) {
    int tid = threadIdx.x;
    int n = blockIdx.x*256 + tid;
    int o = blockIdx.y, b = blockIdx.z;
    float sv = dg_S[((size_t)b*64 + o)*NP + n] + b1[o];
    const float* Pb = dg_P + ((size_t)b*64 + o)*NP;
    const int* ip = dg_idx + ((size_t)b*NP + n)*NK;
    float vals[NK];
    float sum = 0.f, ss = 0.f, mx = -INFINITY;
    #pragma unroll
    for (int j = 0; j < NK; j++) {
        float v = Pb[ip[j]] + sv;
        vals[j] = v;
        sum += v;
        ss = fmaf(v, v, ss);
        mx = fmaxf(mx, v);
    }
    float* dst = dg_h1 + (((size_t)b*64 + o)*NP + n)*NK;
    #pragma unroll
    for (int j4 = 0; j4 < 5; j4++)
        ((float4*)dst)[j4] = make_float4(vals[4*j4], vals[4*j4+1], vals[4*j4+2], vals[4*j4+3]);
    dg_z[((size_t)b*512 + o)*NP + n] = mx;

    #pragma unroll
    for (int d = 1; d < 32; d <<= 1) {
        sum += __shfl_xor_sync(0xffffffffu, sum, d);
        ss  += __shfl_xor_sync(0xffffffffu, ss, d);
    }
    if ((tid & 31) == 0) {
        atomicAdd(&dg_sum[0][o], (double)sum);
        atomicAdd(&dg_ssq[0][o], (double)ss);
    }
}

__global__ void k_finalize(int stage, int C, float cnt,
                           const float* __restrict__ g, const float* __restrict__ be,
                           float* __restrict__ sc, float* __restrict__ sh) {
    int c = threadIdx.x;
    if (c < C) {
        double mu  = dg_sum[stage][c] / (double)cnt;
        double var = dg_ssq[stage][c] / (double)cnt - mu*mu;
        float scale = g[c] * (float)(1.0 / sqrt(var + 1e-5));
        sc[c] = scale;
        sh[c] = be[c] - (float)mu * scale;
    }
}

// ====== edge-domain SGEMM: FFMA2, K-tile 32, fused stats + max ======
template<int MI, bool WRITE>
__global__ void __launch_bounds__(256, 2) k_egemm(
        const float* __restrict__ A, const float* __restrict__ W,
        const float* __restrict__ bias,
        const float* __restrict__ sc, const float* __restrict__ sh,
        float* __restrict__ Out, int M, int K, int stage, int zoff) {
    __shared__ float As[32][160];
    __shared__ float Ws[32][MI*16 + 8];
    int b = blockIdx.z;
    const float* Ab = A + (size_t)b*K*NT;
    int m0 = blockIdx.y*(MI*16), t0 = blockIdx.x*160;
    int tid = threadIdx.x, tx = tid & 15, ty = tid >> 4;

    int ar[5], ac[5];
    #pragma unroll
    for (int i = 0; i < 5; i++) { int e = tid + i*256; ar[i] = e/40; ac[i] = (e%40)*4; }

    ull acc[MI][5];
    #pragma unroll
    for (int i = 0; i < MI; i++)
        #pragma unroll
        for (int q = 0; q < 5; q++) acc[i][q] = 0ull;

    for (int k0 = 0; k0 < K; k0 += 32) {
        // A tile: 32x160 floats = 1280 float4, 5 per thread
        #pragma unroll
        for (int i = 0; i < 5; i++) {
            int r = ar[i];
            float4 v = *(const float4*)(Ab + (size_t)(k0+r)*NT + t0 + ac[i]);
            float s = sc[k0+r], h = sh[k0+r];
            LRELU4(v, s, h);
            *(float4*)&As[r][ac[i]] = v;
        }
        // W tile: (MI*16) x 32, transposed store: MI*128 float4, MI/2 per thread
        #pragma unroll
        for (int i = 0; i < MI/2; i++) {
            int e = tid + i*256; int r = e >> 3, c = (e & 7)*4;
            float4 w = *(const float4*)(W + (size_t)(m0+r)*K + k0 + c);
            Ws[c+0][r] = w.x; Ws[c+1][r] = w.y; Ws[c+2][r] = w.z; Ws[c+3][r] = w.w;
        }
        __syncthreads();
        #pragma unroll 16
        for (int kk = 0; kk < 32; kk++) {
            const ull* arow = (const ull*)&As[kk][tx*10];
            ull ap[5];
            #pragma unroll
            for (int q = 0; q < 5; q++) ap[q] = arow[q];
            float wv[MI];
            #pragma unroll
            for (int h = 0; h < MI; h += 4) {
                float4 wf = *(const float4*)&Ws[kk][ty*MI + h];
                wv[h] = wf.x; wv[h+1] = wf.y; wv[h+2] = wf.z; wv[h+3] = wf.w;
            }
            #pragma unroll
            for (int i = 0; i < MI; i++) {
                ull wp; DUP2(wp, wv[i]);
                #pragma unroll
                for (int q = 0; q < 5; q++) FMA2(acc[i][q], ap[q], wp);
            }
        }
        __syncthreads();
    }

    float* Ob = WRITE ? (Out + (size_t)b*M*NT) : (float*)0;
    #pragma unroll
    for (int i = 0; i < MI; i++) {
        int m = m0 + ty*MI + i;
        float bv = bias[m];
        float sum = 0.f, ss = 0.f, mxv = -INFINITY;
        #pragma unroll
        for (int q = 0; q < 5; q++) {
            float lo, hi;
            UNPK2(lo, hi, acc[i][q]);
            lo += bv; hi += bv;
            if (WRITE)
                *(float2*)(Ob + (size_t)m*NT + t0 + tx*10 + 2*q) = make_float2(lo, hi);
            sum += lo + hi;
            ss = fmaf(lo, lo, ss); ss = fmaf(hi, hi, ss);
            mxv = fmaxf(mxv, fmaxf(lo, hi));
        }
        #pragma unroll
        for (int d = 1; d < 16; d <<= 1) {
            sum += __shfl_xor_sync(0xffffffffu, sum, d);
            ss  += __shfl_xor_sync(0xffffffffu, ss, d);
        }
        if (tx == 0) {
            atomicAdd(&dg_sum[stage][m], (double)sum);
            atomicAdd(&dg_ssq[stage][m], (double)ss);
        }
        float mo = fmaxf(mxv, __shfl_xor_sync(0xffffffffu, mxv, 1));
        if ((tx & 1) == 0)
            dg_z[((size_t)b*512 + zoff + m)*NP + blockIdx.x*8 + (tx >> 1)] = mo;
    }
}

// ====== point-domain SGEMM: FFMA2, K-tile 32, fused stats ======
template<int MI>
__global__ void __launch_bounds__(256, 2) k_pgemm(
        const float* __restrict__ A, const float* __restrict__ W,
        const float* __restrict__ bias,
        const float* __restrict__ sc, const float* __restrict__ sh,
        float* __restrict__ Out, int M, int K, int stage) {
    __shared__ float As[32][128];
    __shared__ float Ws[32][MI*16 + 8];
    int b = blockIdx.z;
    const float* Ab = A + (size_t)b*K*NP;
    float* Ob = Out + (size_t)b*M*NP;
    int m0 = blockIdx.y*(MI*16), t0 = blockIdx.x*128;
    int tid = threadIdx.x, tx = tid & 15, ty = tid >> 4;

    ull acc[MI][4];
    #pragma unroll
    for (int i = 0; i < MI; i++)
        #pragma unroll
        for (int q = 0; q < 4; q++) acc[i][q] = 0ull;

    for (int k0 = 0; k0 < K; k0 += 32) {
        // A tile: 32x128 floats = 1024 float4, 4 per thread
        #pragma unroll
        for (int i = 0; i < 4; i++) {
            int e = tid + i*256; int r = e >> 5, c = (e & 31)*4;
            float4 v = *(const float4*)(Ab + (size_t)(k0+r)*NP + t0 + c);
            float s = sc[k0+r], h = sh[k0+r];
            LRELU4(v, s, h);
            *(float4*)&As[r][c] = v;
        }
        #pragma unroll
        for (int i = 0; i < MI/2; i++) {
            int e = tid + i*256; int r = e >> 3, c = (e & 7)*4;
            float4 w = *(const float4*)(W + (size_t)(m0+r)*K + k0 + c);
            Ws[c+0][r] = w.x; Ws[c+1][r] = w.y; Ws[c+2][r] = w.z; Ws[c+3][r] = w.w;
        }
        __syncthreads();
        #pragma unroll 16
        for (int kk = 0; kk < 32; kk++) {
            const ull* arow = (const ull*)&As[kk][0];
            ull ap[4];
            #pragma unroll
            for (int q = 0; q < 4; q++) ap[q] = arow[tx + 16*q];
            float wv[MI];
            #pragma unroll
            for (int h = 0; h < MI; h += 4) {
                float4 wf = *(const float4*)&Ws[kk][ty*MI + h];
                wv[h] = wf.x; wv[h+1] = wf.y; wv[h+2] = wf.z; wv[h+3] = wf.w;
            }
            #pragma unroll
            for (int i = 0; i < MI; i++) {
                ull wp; DUP2(wp, wv[i]);
                #pragma unroll
                for (int q = 0; q < 4; q++) FMA2(acc[i][q], ap[q], wp);
            }
        }
        __syncthreads();
    }

    #pragma unroll
    for (int i = 0; i < MI; i++) {
        int m = m0 + ty*MI + i;
        float bv = bias[m];
        float sum = 0.f, ss = 0.f;
        #pragma unroll
        for (int q = 0; q < 4; q++) {
            float lo, hi;
            UNPK2(lo, hi, acc[i][q]);
            lo += bv; hi += bv;
            *(float2*)(Ob + (size_t)m*NP + t0 + 2*tx + 32*q) = make_float2(lo, hi);
            sum += lo + hi;
            ss = fmaf(lo, lo, ss); ss = fmaf(hi, hi, ss);
        }
        #pragma unroll
        for (int d = 1; d < 16; d <<= 1) {
            sum += __shfl_xor_sync(0xffffffffu, sum, d);
            ss  += __shfl_xor_sync(0xffffffffu, ss, d);
        }
        if (tx == 0) {
            atomicAdd(&dg_sum[stage][m], (double)sum);
            atomicAdd(&dg_ssq[stage][m], (double)ss);
        }
    }
}

// final bn+lrelu + (B,C,N) -> (B,N,C) transpose
__global__ void k_out(float* __restrict__ out) {
    __shared__ float st[32][33];
    int b = blockIdx.z;
    int c0 = blockIdx.y*32, n0 = blockIdx.x*32;
    int tx = threadIdx.x, ty = threadIdx.y;
    int c = c0 + ty;
    float v = dg_o6[((size_t)b*1024 + c)*NP + n0 + tx];
    v = fmaf(v, dg_sc6[c], dg_sh6[c]);
    st[ty][tx] = v >= 0.f ? v : SLOPE*v;
    __syncthreads();
    out[((size_t)b*NP + n0 + ty)*1024 + c0 + tx] = st[tx][ty];
}

// ---------------- host orchestration ----------------

extern "C" void kernel_launch(void* const* d_in, const int* in_sizes, int n_in,
                              void* d_out, int out_size) {
    (void)in_sizes; (void)n_in; (void)out_size;
    const float* x  = (const float*)d_in[0];
    const float* w1 = (const float*)d_in[1];
    const float* b1 = (const float*)d_in[2];
    const float* g1 = (const float*)d_in[3];
    const float* be1= (const float*)d_in[4];
    const float* w2 = (const float*)d_in[5];
    const float* b2 = (const float*)d_in[6];
    const float* g2 = (const float*)d_in[7];
    const float* be2= (const float*)d_in[8];
    const float* w3 = (const float*)d_in[9];
    const float* b3 = (const float*)d_in[10];
    const float* g3 = (const float*)d_in[11];
    const float* be3= (const float*)d_in[12];
    const float* w4 = (const float*)d_in[13];
    const float* b4 = (const float*)d_in[14];
    const float* g4 = (const float*)d_in[15];
    const float* be4= (const float*)d_in[16];
    const float* w5 = (const float*)d_in[17];
    const float* b5 = (const float*)d_in[18];
    const float* g5 = (const float*)d_in[19];
    const float* be5= (const float*)d_in[20];
    const float* w6 = (const float*)d_in[21];
    const float* b6 = (const float*)d_in[22];
    const float* g6 = (const float*)d_in[23];
    const float* be6= (const float*)d_in[24];

    float *p_h1, *p_h2, *p_h3, *p_z, *p_o5, *p_o6;
    float *p_scZ, *p_shZ, *p_sc5, *p_sh5, *p_sc6, *p_sh6;
    cudaGetSymbolAddress((void**)&p_h1, dg_h1);
    cudaGetSymbolAddress((void**)&p_h2, dg_h2);
    cudaGetSymbolAddress((void**)&p_h3, dg_h3);
    cudaGetSymbolAddress((void**)&p_z,  dg_z);
    cudaGetSymbolAddress((void**)&p_o5, dg_o5);
    cudaGetSymbolAddress((void**)&p_o6, dg_o6);
    cudaGetSymbolAddress((void**)&p_scZ, dg_scZ);
    cudaGetSymbolAddress((void**)&p_shZ, dg_shZ);
    cudaGetSymbolAddress((void**)&p_sc5, dg_sc5);
    cudaGetSymbolAddress((void**)&p_sh5, dg_sh5);
    cudaGetSymbolAddress((void**)&p_sc6, dg_sc6);
    cudaGetSymbolAddress((void**)&p_sh6, dg_sh6);

    const float cntE = (float)(NB*NP*NK);
    const float cntP = (float)(NB*NP);

    k_zero<<<6, 1024>>>();
    k_xx<<<NB, NP>>>(x);
    k_pdist<<<dim3(NP/32, NP/32, NB), dim3(8, 16)>>>(x);
    k_topk<<<NB*NP/8, 256>>>();
    k_ps<<<dim3(NP/256, 64, NB), 256>>>(x, w1);

    k_h1<<<dim3(NP/256, 64, NB), 256>>>(b1);
    k_finalize<<<1, 64>>>(0, 64, cntE, g1, be1, p_scZ, p_shZ);

    // conv2: 64 <- 64 (MI=4)
    k_egemm<4, true><<<dim3(NT/160, 1, NB), 256>>>(p_h1, w2, b2, p_scZ, p_shZ, p_h2, 64, 64, 1, 64);
    k_finalize<<<1, 64>>>(1, 64, cntE, g2, be2, p_scZ + 64, p_shZ + 64);

    // conv3: 128 <- 64 (MI=8)
    k_egemm<8, true><<<dim3(NT/160, 1, NB), 256>>>(p_h2, w3, b3, p_scZ + 64, p_shZ + 64, p_h3, 128, 64, 2, 128);
    k_finalize<<<1, 128>>>(2, 128, cntE, g3, be3, p_scZ + 128, p_shZ + 128);

    // conv4: 256 <- 128, stats+max only (no output tensor)
    k_egemm<8, false><<<dim3(NT/160, 2, NB), 256>>>(p_h3, w4, b4, p_scZ + 128, p_shZ + 128, (float*)0, 256, 128, 3, 256);
    k_finalize<<<1, 256>>>(3, 256, cntE, g4, be4, p_scZ + 256, p_shZ + 256);

    // conv5: 256 <- 512 over points
    k_pgemm<8><<<dim3(NP/128, 2, NB), 256>>>(p_z, w5, b5, p_scZ, p_shZ, p_o5, 256, 512, 4);
    k_finalize<<<1, 256>>>(4, 256, cntP, g5, be5, p_sc5, p_sh5);

    // conv6: 1024 <- 256
    k_pgemm<8><<<dim3(NP/128, 8, NB), 256>>>(p_o5, w6, b6, p_sc5, p_sh5, p_o6, 1024, 256, 5);
    k_finalize<<<1, 1024>>>(5, 1024, cntP, g6, be6, p_sc6, p_sh6);

    k_out<<<dim3(NP/32, 1024/32, NB), dim3(32, 32)>>>((float*)d_out);
}

// round 10
// speedup vs baseline: 1.8036x; 1.0960x over previous
#include <cuda_runtime.h>
#include <math.h>

#define NB 8
#define ND 60
#define NP 1024
#define NK 20
#define NT (NP*NK)
#define SLOPE 0.2f

typedef unsigned long long ull;

// ---------------- device scratch ----------------
static __device__ float dg_pd[NB*NP*NP];
static __device__ float dg_xx[NB*NP];
static __device__ int   dg_idx[NB*NP*NK];
static __device__ float dg_P[NB*64*NP];
static __device__ float dg_S[NB*64*NP];
static __device__ float dg_h1[NB*64*NT];
static __device__ float dg_h2[NB*64*NT];
static __device__ float dg_h3[NB*128*NT];
static __device__ float dg_z [NB*512*NP];
static __device__ float dg_o5[NB*256*NP];
static __device__ float dg_o6[NB*1024*NP];
static __device__ double dg_sum[6][1024];
static __device__ double dg_ssq[6][1024];
static __device__ float dg_scZ[512], dg_shZ[512];
static __device__ float dg_sc5[256], dg_sh5[256];
static __device__ float dg_sc6[1024], dg_sh6[1024];
// pre-transposed weights Wt[k][m]
static __device__ float dg_w2t[64*64];
static __device__ float dg_w3t[64*128];
static __device__ float dg_w4t[128*256];
static __device__ float dg_w5t[512*256];
static __device__ float dg_w6t[256*1024];

// packed fp32x2 FMA (sm_103a) — exact fp32 numerics per lane, 2x rate
#define FMA2(d, a, bb) asm("fma.rn.f32x2 %0, %1, %2, %0;" : "+l"(d) : "l"(a), "l"(bb))
#define DUP2(d, f)     asm("mov.b64 %0, {%1, %1};" : "=l"(d) : "f"(f))
#define UNPK2(lo, hi, d) asm("mov.b64 {%0, %1}, %2;" : "=f"(lo), "=f"(hi) : "l"(d))

#define LRELU4(v, s, h)                                           \
    v.x = fmaf(v.x, s, h); v.x = v.x >= 0.f ? v.x : SLOPE*v.x;    \
    v.y = fmaf(v.y, s, h); v.y = v.y >= 0.f ? v.y : SLOPE*v.y;    \
    v.z = fmaf(v.z, s, h); v.z = v.z >= 0.f ? v.z : SLOPE*v.z;    \
    v.w = fmaf(v.w, s, h); v.w = v.w >= 0.f ? v.w : SLOPE*v.w;

// cp.async helpers (sm_80+ baseline PTX — valid on plain compute_103)
#define CPA16(dst_u32, gptr) \
    asm volatile("cp.async.ca.shared.global [%0], [%1], 16;" :: "r"(dst_u32), "l"(gptr) : "memory")
#define CPA_COMMIT() asm volatile("cp.async.commit_group;" ::: "memory")
#define CPA_WAIT0()  asm volatile("cp.async.wait_group 0;" ::: "memory")
#define CPA_WAIT1()  asm volatile("cp.async.wait_group 1;" ::: "memory")

static __device__ __forceinline__ unsigned smem_u32(const void* p) {
    unsigned a;
    asm("{ .reg .u64 t; cvta.to.shared.u64 t, %1; cvt.u32.u64 %0, t; }" : "=r"(a) : "l"(p));
    return a;
}

// ---------------- small kernels ----------------

__global__ void k_zero() {
    int i = blockIdx.x*1024 + threadIdx.x;
    ((double*)dg_sum)[i] = 0.0;
    ((double*)dg_ssq)[i] = 0.0;
}

// w[m][k] -> wt[k][m]; dims multiples of 32
__global__ void k_wt(const float* __restrict__ w, float* __restrict__ wt, int M, int K) {
    __shared__ float t[32][33];
    int k0 = blockIdx.x*32, m0 = blockIdx.y*32;
    int tx = threadIdx.x, ty = threadIdx.y;
    t[ty][tx] = w[(size_t)(m0+ty)*K + k0 + tx];
    __syncthreads();
    wt[(size_t)(k0+ty)*M + m0 + tx] = t[tx][ty];
}

__global__ void k_xx(const float* __restrict__ x) {
    int b = blockIdx.x, n = threadIdx.x;
    float s = 0.f;
    #pragma unroll
    for (int d = 0; d < ND; d++) {
        float v = x[((size_t)b*ND + d)*NP + n];
        s = fmaf(v, v, s);
    }
    dg_xx[b*NP + n] = s;
}

// pd[b,n,m] = 2*dot(x_n,x_m) - xx_n - xx_m
__global__ void __launch_bounds__(128) k_pdist(const float* __restrict__ x) {
    __shared__ float sn[ND][32], sm[ND][32];
    int b = blockIdx.z;
    int n0 = blockIdx.y*32, m0 = blockIdx.x*32;
    int tx = threadIdx.x, ty = threadIdx.y;
    int tid = ty*8 + tx;
    for (int e = tid; e < ND*32; e += 128) {
        int d = e >> 5, c = e & 31;
        size_t base = ((size_t)b*ND + d)*NP;
        sn[d][c] = x[base + n0 + c];
        sm[d][c] = x[base + m0 + c];
    }
    __syncthreads();
    ull acc[2][2] = {{0ull,0ull},{0ull,0ull}};
    #pragma unroll
    for (int d = 0; d < ND; d++) {
        ull sn2 = *(const ull*)&sn[d][ty*2];
        float nlo, nhi; UNPK2(nlo, nhi, sn2);
        ull dlo, dhi; DUP2(dlo, nlo); DUP2(dhi, nhi);
        ull mp0 = *(const ull*)&sm[d][tx*4];
        ull mp1 = *(const ull*)&sm[d][tx*4+2];
        FMA2(acc[0][0], mp0, dlo); FMA2(acc[0][1], mp1, dlo);
        FMA2(acc[1][0], mp0, dhi); FMA2(acc[1][1], mp1, dhi);
    }
    float xm[4];
    #pragma unroll
    for (int j = 0; j < 4; j++) xm[j] = dg_xx[b*NP + m0 + tx*4 + j];
    #pragma unroll
    for (int i = 0; i < 2; i++) {
        int n = n0 + ty*2 + i;
        float xn = dg_xx[b*NP + n];
        float v0, v1, v2, v3;
        UNPK2(v0, v1, acc[i][0]);
        UNPK2(v2, v3, acc[i][1]);
        float4 o = make_float4(2.f*v0 - xn - xm[0], 2.f*v1 - xn - xm[1],
                               2.f*v2 - xn - xm[2], 2.f*v3 - xn - xm[3]);
        *(float4*)(dg_pd + ((size_t)b*NP + n)*NP + m0 + tx*4) = o;
    }
}

// warp-per-row top-20 via per-lane bitonic sort of packed (value,idx) keys
__global__ void k_topk() {
    int warp = threadIdx.x >> 5, lane = threadIdx.x & 31;
    int row = blockIdx.x*8 + warp;
    const float* rp = dg_pd + (size_t)row*NP;
    ull k[32];
    #pragma unroll
    for (int i = 0; i < 8; i++) {
        float4 t = *(const float4*)(rp + i*128 + lane*4);
        float vv[4] = {t.x, t.y, t.z, t.w};
        #pragma unroll
        for (int j = 0; j < 4; j++) {
            unsigned fb = __float_as_uint(vv[j]);
            unsigned u = (fb & 0x80000000u) ? ~fb : (fb | 0x80000000u);
            unsigned idx = (unsigned)(i*128 + lane*4 + j);
            k[i*4+j] = ((ull)u << 32) | (ull)(0xFFFFFFFFu - idx);
        }
    }
    #pragma unroll
    for (int sz = 2; sz <= 32; sz <<= 1) {
        #pragma unroll
        for (int st = sz >> 1; st > 0; st >>= 1) {
            #pragma unroll
            for (int i = 0; i < 32; i++) {
                int j = i ^ st;
                if (j > i) {
                    bool sw = ((i & sz) == 0) ? (k[i] < k[j]) : (k[i] > k[j]);
                    if (sw) { ull t = k[i]; k[i] = k[j]; k[j] = t; }
                }
            }
        }
    }
    int* outp = dg_idx + (size_t)row*NK;
    #pragma unroll
    for (int t = 0; t < NK; t++) {
        ull best = k[0];
        #pragma unroll
        for (int d = 16; d; d >>= 1) {
            ull o = __shfl_xor_sync(0xffffffffu, best, d);
            if (o > best) best = o;
        }
        if (lane == 0) outp[t] = (int)(0xFFFFFFFFu - (unsigned)(best & 0xFFFFFFFFull));
        if (k[0] == best) {
            #pragma unroll
            for (int j = 0; j < 20; j++) k[j] = k[j+1];
        }
    }
}

__global__ void k_ps(const float* __restrict__ x, const float* __restrict__ w1) {
    __shared__ float wa[ND], ws[ND];
    int o = blockIdx.y, b = blockIdx.z, tid = threadIdx.x;
    if (tid < ND) {
        float a = w1[o*120 + tid];
        wa[tid] = a;
        ws[tid] = w1[o*120 + 60 + tid] - a;
    }
    __syncthreads();
    int n = blockIdx.x*256 + tid;
    float p = 0.f, s = 0.f;
    #pragma unroll
    for (int d = 0; d < ND; d++) {
        float xv = x[((size_t)b*ND + d)*NP + n];
        p = fmaf(wa[d], xv, p);
        s = fmaf(ws[d], xv, s);
    }
    dg_P[((size_t)b*64 + o)*NP + n] = p;
    dg_S[((size_t)b*64 + o)*NP + n] = s;
}

__global__ void k_h1(const float* __restrict__ b1) {
    int tid = threadIdx.x;
    int n = blockIdx.x*256 + tid;
    int o = blockIdx.y, b = blockIdx.z;
    float sv = dg_S[((size_t)b*64 + o)*NP + n] + b1[o];
    const float* Pb = dg_P + ((size_t)b*64 + o)*NP;
    const int* ip = dg_idx + ((size_t)b*NP + n)*NK;
    float vals[NK];
    float sum = 0.f, ss = 0.f, mx = -INFINITY;
    #pragma unroll
    for (int j = 0; j < NK; j++) {
        float v = Pb[ip[j]] + sv;
        vals[j] = v;
        sum += v;
        ss = fmaf(v, v, ss);
        mx = fmaxf(mx, v);
    }
    float* dst = dg_h1 + (((size_t)b*64 + o)*NP + n)*NK;
    #pragma unroll
    for (int j4 = 0; j4 < 5; j4++)
        ((float4*)dst)[j4] = make_float4(vals[4*j4], vals[4*j4+1], vals[4*j4+2], vals[4*j4+3]);
    dg_z[((size_t)b*512 + o)*NP + n] = mx;

    #pragma unroll
    for (int d = 1; d < 32; d <<= 1) {
        sum += __shfl_xor_sync(0xffffffffu, sum, d);
        ss  += __shfl_xor_sync(0xffffffffu, ss, d);
    }
    if ((tid & 31) == 0) {
        atomicAdd(&dg_sum[0][o], (double)sum);
        atomicAdd(&dg_ssq[0][o], (double)ss);
    }
}

__global__ void k_finalize(int stage, int C, float cnt,
                           const float* __restrict__ g, const float* __restrict__ be,
                           float* __restrict__ sc, float* __restrict__ sh) {
    int c = threadIdx.x;
    if (c < C) {
        double mu  = dg_sum[stage][c] / (double)cnt;
        double var = dg_ssq[stage][c] / (double)cnt - mu*mu;
        float scale = g[c] * (float)(1.0 / sqrt(var + 1e-5));
        sc[c] = scale;
        sh[c] = be[c] - (float)mu * scale;
    }
}

// ====== edge-domain SGEMM: FFMA2, cp.async double-buffered (in-place xform),
//        fused stats + max. Static smem only. ======
template<int MI, bool WRITE>
__global__ void __launch_bounds__(256, 2) k_egemm(
        const float* __restrict__ A, const float* __restrict__ Wt,
        const float* __restrict__ bias,
        const float* __restrict__ sc, const float* __restrict__ sh,
        float* __restrict__ Out, int M, int K, int stage, int zoff) {
    __shared__ float As[2][16*160];
    __shared__ float Ws[2][16*MI*16];
    const int WT = MI*16;
    unsigned Asu = smem_u32(As);
    unsigned Wsu = smem_u32(Ws);
    int b = blockIdx.z;
    const float* Ab = A + (size_t)b*K*NT;
    int m0 = blockIdx.y*WT, t0 = blockIdx.x*160;
    int tid = threadIdx.x, tx = tid & 15, ty = tid >> 4;
    int KT = K >> 4;

    ull acc[MI][5];
    #pragma unroll
    for (int i = 0; i < MI; i++)
        #pragma unroll
        for (int q = 0; q < 5; q++) acc[i][q] = 0ull;

#define EG_LOAD(KT_IDX, BI) do { \
        int k0_ = (KT_IDX) << 4; \
        _Pragma("unroll") \
        for (int i_ = 0; i_ < 3; i_++) { int e_ = tid + i_*256; if (e_ < 640) { \
            int r_ = e_/40, c_ = (e_%40)*4; \
            CPA16(Asu + (unsigned)((BI)*2560 + r_*160 + c_)*4u, \
                  Ab + (size_t)(k0_+r_)*NT + t0 + c_); } } \
        _Pragma("unroll") \
        for (int i_ = 0; i_ < (MI > 4 ? 2 : 1); i_++) { int e_ = tid + i_*256; if (e_ < MI*64) { \
            int r_ = e_/(MI*4), c_ = (e_%(MI*4))*4; \
            CPA16(Wsu + (unsigned)((BI)*16*WT + r_*WT + c_)*4u, \
                  Wt + (size_t)(k0_+r_)*M + m0 + c_); } } \
        CPA_COMMIT(); \
    } while (0)

#define EG_XFORM(BI, K0) do { \
        _Pragma("unroll") \
        for (int i_ = 0; i_ < 3; i_++) { int e_ = tid + i_*256; if (e_ < 640) { \
            int r_ = e_/40, c_ = (e_%40)*4; \
            float4 v_ = *(float4*)&As[BI][r_*160 + c_]; \
            float s_ = sc[(K0)+r_], h_ = sh[(K0)+r_]; \
            LRELU4(v_, s_, h_); \
            *(float4*)&As[BI][r_*160 + c_] = v_; } } \
    } while (0)

    EG_LOAD(0, 0);
    EG_LOAD(1, 1);
    CPA_WAIT1();            // tile 0 arrived
    __syncthreads();
    EG_XFORM(0, 0);
    __syncthreads();

    for (int kt = 0; kt < KT; kt++) {
        int cb = kt & 1, nb = cb ^ 1;
        const float* An = As[cb];
        const float* Wn = Ws[cb];
        #pragma unroll
        for (int kk = 0; kk < 16; kk++) {
            const ull* arow = (const ull*)&An[kk*160 + tx*10];
            ull ap[5];
            #pragma unroll
            for (int q = 0; q < 5; q++) ap[q] = arow[q];
            float wv[MI];
            #pragma unroll
            for (int h = 0; h < MI; h += 4) {
                float4 wf = *(const float4*)&Wn[kk*WT + ty*MI + h];
                wv[h] = wf.x; wv[h+1] = wf.y; wv[h+2] = wf.z; wv[h+3] = wf.w;
            }
            #pragma unroll
            for (int i = 0; i < MI; i++) {
                ull wp; DUP2(wp, wv[i]);
                #pragma unroll
                for (int q = 0; q < 5; q++) FMA2(acc[i][q], ap[q], wp);
            }
        }
        if (kt + 1 < KT) {
            CPA_WAIT0();        // tile kt+1 raw data present
            __syncthreads();    // all threads done computing on buffers [cb]
            EG_XFORM(nb, (kt+1) << 4);
            if (kt + 2 < KT) EG_LOAD(kt+2, cb);
            __syncthreads();    // transformed tile visible
        }
    }
#undef EG_LOAD
#undef EG_XFORM

    float* Ob = WRITE ? (Out + (size_t)b*M*NT) : (float*)0;
    #pragma unroll
    for (int i = 0; i < MI; i++) {
        int m = m0 + ty*MI + i;
        float bv = bias[m];
        float sum = 0.f, ss = 0.f, mxv = -INFINITY;
        #pragma unroll
        for (int q = 0; q < 5; q++) {
            float lo, hi;
            UNPK2(lo, hi, acc[i][q]);
            lo += bv; hi += bv;
            if (WRITE)
                *(float2*)(Ob + (size_t)m*NT + t0 + tx*10 + 2*q) = make_float2(lo, hi);
            sum += lo + hi;
            ss = fmaf(lo, lo, ss); ss = fmaf(hi, hi, ss);
            mxv = fmaxf(mxv, fmaxf(lo, hi));
        }
        #pragma unroll
        for (int d = 1; d < 16; d <<= 1) {
            sum += __shfl_xor_sync(0xffffffffu, sum, d);
            ss  += __shfl_xor_sync(0xffffffffu, ss, d);
        }
        if (tx == 0) {
            atomicAdd(&dg_sum[stage][m], (double)sum);
            atomicAdd(&dg_ssq[stage][m], (double)ss);
        }
        float mo = fmaxf(mxv, __shfl_xor_sync(0xffffffffu, mxv, 1));
        if ((tx & 1) == 0)
            dg_z[((size_t)b*512 + zoff + m)*NP + blockIdx.x*8 + (tx >> 1)] = mo;
    }
}

// ====== point-domain SGEMM: FFMA2, cp.async double-buffered (in-place xform),
//        fused stats. Static smem only. ======
template<int MI>
__global__ void __launch_bounds__(256, 2) k_pgemm(
        const float* __restrict__ A, const float* __restrict__ Wt,
        const float* __restrict__ bias,
        const float* __restrict__ sc, const float* __restrict__ sh,
        float* __restrict__ Out, int M, int K, int stage) {
    __shared__ float As[2][16*128];
    __shared__ float Ws[2][16*MI*16];
    const int WT = MI*16;
    unsigned Asu = smem_u32(As);
    unsigned Wsu = smem_u32(Ws);
    int b = blockIdx.z;
    const float* Ab = A + (size_t)b*K*NP;
    float* Ob = Out + (size_t)b*M*NP;
    int m0 = blockIdx.y*WT, t0 = blockIdx.x*128;
    int tid = threadIdx.x, tx = tid & 15, ty = tid >> 4;
    int KT = K >> 4;

    ull acc[MI][4];
    #pragma unroll
    for (int i = 0; i < MI; i++)
        #pragma unroll
        for (int q = 0; q < 4; q++) acc[i][q] = 0ull;

#define PG_LOAD(KT_IDX, BI) do { \
        int k0_ = (KT_IDX) << 4; \
        _Pragma("unroll") \
        for (int i_ = 0; i_ < 2; i_++) { int e_ = tid + i_*256; \
            int r_ = e_ >> 5, c_ = (e_ & 31)*4; \
            CPA16(Asu + (unsigned)((BI)*2048 + r_*128 + c_)*4u, \
                  Ab + (size_t)(k0_+r_)*NP + t0 + c_); } \
        _Pragma("unroll") \
        for (int i_ = 0; i_ < (MI > 4 ? 2 : 1); i_++) { int e_ = tid + i_*256; if (e_ < MI*64) { \
            int r_ = e_/(MI*4), c_ = (e_%(MI*4))*4; \
            CPA16(Wsu + (unsigned)((BI)*16*WT + r_*WT + c_)*4u, \
                  Wt + (size_t)(k0_+r_)*M + m0 + c_); } } \
        CPA_COMMIT(); \
    } while (0)

#define PG_XFORM(BI, K0) do { \
        _Pragma("unroll") \
        for (int i_ = 0; i_ < 2; i_++) { int e_ = tid + i_*256; \
            int r_ = e_ >> 5, c_ = (e_ & 31)*4; \
            float4 v_ = *(float4*)&As[BI][r_*128 + c_]; \
            float s_ = sc[(K0)+r_], h_ = sh[(K0)+r_]; \
            LRELU4(v_, s_, h_); \
            *(float4*)&As[BI][r_*128 + c_] = v_; } \
    } while (0)

    PG_LOAD(0, 0);
    PG_LOAD(1, 1);
    CPA_WAIT1();
    __syncthreads();
    PG_XFORM(0, 0);
    __syncthreads();

    for (int kt = 0; kt < KT; kt++) {
        int cb = kt & 1, nb = cb ^ 1;
        const float* An = As[cb];
        const float* Wn = Ws[cb];
        #pragma unroll
        for (int kk = 0; kk < 16; kk++) {
            const ull* arow = (const ull*)&An[kk*128];
            ull ap[4];
            #pragma unroll
            for (int q = 0; q < 4; q++) ap[q] = arow[tx + 16*q];
            float wv[MI];
            #pragma unroll
            for (int h = 0; h < MI; h += 4) {
                float4 wf = *(const float4*)&Wn[kk*WT + ty*MI + h];
                wv[h] = wf.x; wv[h+1] = wf.y; wv[h+2] = wf.z; wv[h+3] = wf.w;
            }
            #pragma unroll
            for (int i = 0; i < MI; i++) {
                ull wp; DUP2(wp, wv[i]);
                #pragma unroll
                for (int q = 0; q < 4; q++) FMA2(acc[i][q], ap[q], wp);
            }
        }
        if (kt + 1 < KT) {
            CPA_WAIT0();
            __syncthreads();
            PG_XFORM(nb, (kt+1) << 4);
            if (kt + 2 < KT) PG_LOAD(kt+2, cb);
            __syncthreads();
        }
    }
#undef PG_LOAD
#undef PG_XFORM

    #pragma unroll
    for (int i = 0; i < MI; i++) {
        int m = m0 + ty*MI + i;
        float bv = bias[m];
        float sum = 0.f, ss = 0.f;
        #pragma unroll
        for (int q = 0; q < 4; q++) {
            float lo, hi;
            UNPK2(lo, hi, acc[i][q]);
            lo += bv; hi += bv;
            *(float2*)(Ob + (size_t)m*NP + t0 + 2*tx + 32*q) = make_float2(lo, hi);
            sum += lo + hi;
            ss = fmaf(lo, lo, ss); ss = fmaf(hi, hi, ss);
        }
        #pragma unroll
        for (int d = 1; d < 16; d <<= 1) {
            sum += __shfl_xor_sync(0xffffffffu, sum, d);
            ss  += __shfl_xor_sync(0xffffffffu, ss, d);
        }
        if (tx == 0) {
            atomicAdd(&dg_sum[stage][m], (double)sum);
            atomicAdd(&dg_ssq[stage][m], (double)ss);
        }
    }
}

// final bn+lrelu + (B,C,N) -> (B,N,C) transpose
__global__ void k_out(float* __restrict__ out) {
    __shared__ float st[32][33];
    int b = blockIdx.z;
    int c0 = blockIdx.y*32, n0 = blockIdx.x*32;
    int tx = threadIdx.x, ty = threadIdx.y;
    int c = c0 + ty;
    float v = dg_o6[((size_t)b*1024 + c)*NP + n0 + tx];
    v = fmaf(v, dg_sc6[c], dg_sh6[c]);
    st[ty][tx] = v >= 0.f ? v : SLOPE*v;
    __syncthreads();
    out[((size_t)b*NP + n0 + ty)*1024 + c0 + tx] = st[tx][ty];
}

// ---------------- host orchestration ----------------

extern "C" void kernel_launch(void* const* d_in, const int* in_sizes, int n_in,
                              void* d_out, int out_size) {
    (void)in_sizes; (void)n_in; (void)out_size;
    const float* x  = (const float*)d_in[0];
    const float* w1 = (const float*)d_in[1];
    const float* b1 = (const float*)d_in[2];
    const float* g1 = (const float*)d_in[3];
    const float* be1= (const float*)d_in[4];
    const float* w2 = (const float*)d_in[5];
    const float* b2 = (const float*)d_in[6];
    const float* g2 = (const float*)d_in[7];
    const float* be2= (const float*)d_in[8];
    const float* w3 = (const float*)d_in[9];
    const float* b3 = (const float*)d_in[10];
    const float* g3 = (const float*)d_in[11];
    const float* be3= (const float*)d_in[12];
    const float* w4 = (const float*)d_in[13];
    const float* b4 = (const float*)d_in[14];
    const float* g4 = (const float*)d_in[15];
    const float* be4= (const float*)d_in[16];
    const float* w5 = (const float*)d_in[17];
    const float* b5 = (const float*)d_in[18];
    const float* g5 = (const float*)d_in[19];
    const float* be5= (const float*)d_in[20];
    const float* w6 = (const float*)d_in[21];
    const float* b6 = (const float*)d_in[22];
    const float* g6 = (const float*)d_in[23];
    const float* be6= (const float*)d_in[24];

    float *p_h1, *p_h2, *p_h3, *p_z, *p_o5, *p_o6;
    float *p_scZ, *p_shZ, *p_sc5, *p_sh5, *p_sc6, *p_sh6;
    float *p_w2t, *p_w3t, *p_w4t, *p_w5t, *p_w6t;
    cudaGetSymbolAddress((void**)&p_h1, dg_h1);
    cudaGetSymbolAddress((void**)&p_h2, dg_h2);
    cudaGetSymbolAddress((void**)&p_h3, dg_h3);
    cudaGetSymbolAddress((void**)&p_z,  dg_z);
    cudaGetSymbolAddress((void**)&p_o5, dg_o5);
    cudaGetSymbolAddress((void**)&p_o6, dg_o6);
    cudaGetSymbolAddress((void**)&p_scZ, dg_scZ);
    cudaGetSymbolAddress((void**)&p_shZ, dg_shZ);
    cudaGetSymbolAddress((void**)&p_sc5, dg_sc5);
    cudaGetSymbolAddress((void**)&p_sh5, dg_sh5);
    cudaGetSymbolAddress((void**)&p_sc6, dg_sc6);
    cudaGetSymbolAddress((void**)&p_sh6, dg_sh6);
    cudaGetSymbolAddress((void**)&p_w2t, dg_w2t);
    cudaGetSymbolAddress((void**)&p_w3t, dg_w3t);
    cudaGetSymbolAddress((void**)&p_w4t, dg_w4t);
    cudaGetSymbolAddress((void**)&p_w5t, dg_w5t);
    cudaGetSymbolAddress((void**)&p_w6t, dg_w6t);

    const float cntE = (float)(NB*NP*NK);
    const float cntP = (float)(NB*NP);

    k_zero<<<6, 1024>>>();
    k_wt<<<dim3(64/32, 64/32), dim3(32, 32)>>>(w2, p_w2t, 64, 64);
    k_wt<<<dim3(64/32, 128/32), dim3(32, 32)>>>(w3, p_w3t, 128, 64);
    k_wt<<<dim3(128/32, 256/32), dim3(32, 32)>>>(w4, p_w4t, 256, 128);
    k_wt<<<dim3(512/32, 256/32), dim3(32, 32)>>>(w5, p_w5t, 256, 512);
    k_wt<<<dim3(256/32, 1024/32), dim3(32, 32)>>>(w6, p_w6t, 1024, 256);
    k_xx<<<NB, NP>>>(x);
    k_pdist<<<dim3(NP/32, NP/32, NB), dim3(8, 16)>>>(x);
    k_topk<<<NB*NP/8, 256>>>();
    k_ps<<<dim3(NP/256, 64, NB), 256>>>(x, w1);

    k_h1<<<dim3(NP/256, 64, NB), 256>>>(b1);
    k_finalize<<<1, 64>>>(0, 64, cntE, g1, be1, p_scZ, p_shZ);

    // conv2: 64 <- 64 (MI=4)
    k_egemm<4, true><<<dim3(NT/160, 1, NB), 256>>>(p_h1, p_w2t, b2, p_scZ, p_shZ, p_h2, 64, 64, 1, 64);
    k_finalize<<<1, 64>>>(1, 64, cntE, g2, be2, p_scZ + 64, p_shZ + 64);

    // conv3: 128 <- 64 (MI=8)
    k_egemm<8, true><<<dim3(NT/160, 1, NB), 256>>>(p_h2, p_w3t, b3, p_scZ + 64, p_shZ + 64, p_h3, 128, 64, 2, 128);
    k_finalize<<<1, 128>>>(2, 128, cntE, g3, be3, p_scZ + 128, p_shZ + 128);

    // conv4: 256 <- 128, stats+max only (no output tensor)
    k_egemm<8, false><<<dim3(NT/160, 2, NB), 256>>>(p_h3, p_w4t, b4, p_scZ + 128, p_shZ + 128, (float*)0, 256, 128, 3, 256);
    k_finalize<<<1, 256>>>(3, 256, cntE, g4, be4, p_scZ + 256, p_shZ + 256);

    // conv5: 256 <- 512 over points
    k_pgemm<8><<<dim3(NP/128, 2, NB), 256>>>(p_z, p_w5t, b5, p_scZ, p_shZ, p_o5, 256, 512, 4);
    k_finalize<<<1, 256>>>(4, 256, cntP, g5, be5, p_sc5, p_sh5);

    // conv6: 1024 <- 256
    k_pgemm<8><<<dim3(NP/128, 8, NB), 256>>>(p_o5, p_w6t, b6, p_sc5, p_sh5, p_o6, 1024, 256, 5);
    k_finalize<<<1, 1024>>>(5, 1024, cntP, g6, be6, p_sc6, p_sh6);

    k_out<<<dim3(NP/32, 1024/32, NB), dim3(32, 32)>>>((float*)d_out);
}